// round 13
// baseline (speedup 1.0000x reference)
#include <cuda_runtime.h>
#include <cuda_fp16.h>
#include <cstdint>

#define H   1024
#define NB  16
#define TSTEPS 256
#define BT  4096      // B*T
#define N1  4096      // 4*H
#define NV  32000
#define K2  2048      // p3 logical K: [Ah | Al]
#define K1  3072      // p1 logical K: [xh | xl | xh] (storage wraps to 2048)

typedef unsigned long long u64;

// ---------------- scratch (device globals; no allocations allowed) ----------
__device__ float g_xall[(size_t)BT * N1];       // gate pre-activations (64 MB)
__device__ float g_h[H * NB];                   // current h [k][b] fp32
__device__ unsigned g_bar;                      // grid barrier
__device__ __half g_a2h[(size_t)BT * K2];       // p3 A: [m][Ah|Al] (16.8 MB)
__device__ __half g_b2h[(size_t)H * NV];        // p3 B: [Bh] 1024 rows (65.5 MB)
__device__ __half g_a1h[(size_t)BT * 2048];     // p1 A: [m][xh|xl] (16.8 MB)
__device__ __half g_b1h[(size_t)2048 * N1];     // p1 B: [Wh;Wl] (16.8 MB)
__device__ float  g_bias1[N1];                  // concat gate biases

// ---------------- packed f32x2 helpers --------------------------------------
__device__ __forceinline__ u64 pk2(float lo, float hi) {
    u64 r; asm("mov.b64 %0, {%1,%2};" : "=l"(r) : "f"(lo), "f"(hi)); return r;
}
__device__ __forceinline__ void fma2(u64 &d, u64 a, u64 b) {
    asm("fma.rn.f32x2 %0, %1, %2, %0;" : "+l"(d) : "l"(a), "l"(b));
}
__device__ __forceinline__ void upk2(float &lo, float &hi, u64 v) {
    asm("mov.b64 {%0,%1}, %2;" : "=f"(lo), "=f"(hi) : "l"(v));
}
__device__ __forceinline__ uint32_t smem_u32(const void* p) {
    uint32_t a;
    asm("{ .reg .u64 t; cvta.to.shared.u64 t, %1; cvt.u32.u64 %0, t; }"
        : "=r"(a) : "l"(p));
    return a;
}

// ---------------- cp.async helpers ------------------------------------------
__device__ __forceinline__ void cp16(uint32_t dst, const void* src) {
    asm volatile("cp.async.cg.shared.global [%0], [%1], 16;"
                 :: "r"(dst), "l"(src));
}
__device__ __forceinline__ void cp_commit() {
    asm volatile("cp.async.commit_group;");
}
template<int N> __device__ __forceinline__ void cp_wait() {
    asm volatile("cp.async.wait_group %0;" :: "n"(N));
}

// ---------------- mma helpers ------------------------------------------------
__device__ __forceinline__ void ldsm4(uint32_t* r, uint32_t addr) {
    asm volatile("ldmatrix.sync.aligned.m8n8.x4.shared.b16 {%0,%1,%2,%3}, [%4];"
                 : "=r"(r[0]), "=r"(r[1]), "=r"(r[2]), "=r"(r[3]) : "r"(addr));
}
__device__ __forceinline__ void ldsm4t(uint32_t* r, uint32_t addr) {
    asm volatile("ldmatrix.sync.aligned.m8n8.x4.trans.shared.b16 {%0,%1,%2,%3}, [%4];"
                 : "=r"(r[0]), "=r"(r[1]), "=r"(r[2]), "=r"(r[3]) : "r"(addr));
}
__device__ __forceinline__ void mma16816(float* d, const uint32_t* a,
                                         const uint32_t* b) {
    asm volatile(
        "mma.sync.aligned.m16n8k16.row.col.f32.f16.f16.f32 "
        "{%0,%1,%2,%3}, {%4,%5,%6,%7}, {%8,%9}, {%0,%1,%2,%3};"
        : "+f"(d[0]), "+f"(d[1]), "+f"(d[2]), "+f"(d[3])
        : "r"(a[0]), "r"(a[1]), "r"(a[2]), "r"(a[3]), "r"(b[0]), "r"(b[1]));
}

// ---------------- conversion kernels ----------------------------------------
__global__ void conv_w2(const float* __restrict__ w) {
    size_t idx = (size_t)blockIdx.x * blockDim.x + threadIdx.x;
    if (idx >= (size_t)H * NV) return;
    g_b2h[idx] = __float2half(w[idx]);
}

__global__ void conv_w1(const float* __restrict__ wf, const float* __restrict__ wi,
                        const float* __restrict__ wc, const float* __restrict__ wo,
                        const float* __restrict__ bf_, const float* __restrict__ bi_,
                        const float* __restrict__ bc_, const float* __restrict__ bo_) {
    size_t idx = (size_t)blockIdx.x * blockDim.x + threadIdx.x;
    if (idx < N1) {
        int g = (int)(idx >> 10), j = (int)(idx & 1023);
        const float* bs = (g == 0) ? bf_ : (g == 1) ? bi_ : (g == 2) ? bc_ : bo_;
        g_bias1[idx] = bs[j];
    }
    if (idx >= (size_t)H * N1) return;
    int k = (int)(idx >> 12);
    int col = (int)(idx & 4095);
    int g = col >> 10, j = col & 1023;
    const float* w = (g == 0) ? wf : (g == 1) ? wi : (g == 2) ? wc : wo;
    float x = w[(size_t)k * H + j];
    __half hi = __float2half(x);
    __half lo = __float2half(x - __half2float(hi));
    g_b1h[(size_t)k * N1 + col] = hi;
    g_b1h[(size_t)(k + 1024) * N1 + col] = lo;
}

__global__ void conv_x(const int* __restrict__ tokens, const float* __restrict__ emb) {
    size_t idx = (size_t)blockIdx.x * blockDim.x + threadIdx.x;
    if (idx >= (size_t)BT * H) return;
    size_t m = idx >> 10, k = idx & 1023;
    int tok = __ldg(&tokens[m]);
    float x = __ldg(&emb[(size_t)tok * H + k]);
    __half hi = __float2half(x);
    __half lo = __float2half(x - __half2float(hi));
    __half* row = g_a1h + m * 2048;
    row[k] = hi; row[k + 1024] = lo;
}

// ---------------- shared GEMM tile constants --------------------------------
#define GM_BM 128
#define GM_BK 32
#define GM_STAGES 4
#define GA_STRIDE 40
#define GB_STRIDE 136
#define GA_ST_BYTES (GM_BM * GA_STRIDE * 2)
#define GB_ST_BYTES (GM_BK * GB_STRIDE * 2)
#define GM_STAGE_BYTES (GA_ST_BYTES + GB_ST_BYTES)
#define GM_SMEM (GM_STAGES * GM_STAGE_BYTES)   // 75776 -> 2 CTA/SM

// ---------------- p1: mma GEMM 128x128x32, 4-stage, 2 CTA/SM ----------------
__global__ void __launch_bounds__(256, 2) gemm_p1_mma()
{
    constexpr int kiters = K1 / GM_BK;        // 96
    extern __shared__ char dynsm[];
    const int tid  = threadIdx.x;
    const int wid  = tid >> 5;
    const int lane = tid & 31;
    const int m0 = blockIdx.x * GM_BM;
    const int n0 = blockIdx.y * 128;
    const int m_w = (wid & 3) * 32;
    const int n_w = (wid >> 2) * 64;
    const uint32_t smb = smem_u32(dynsm);

    const int a_row = tid >> 2,  a_seg = tid & 3;
    const int b_row = tid >> 4,  b_seg = tid & 15;

    auto load_stage = [&](int chunk, int s) {
        const int kc0 = chunk * GM_BK;
        const uint32_t sa = smb + s * GM_STAGE_BYTES;
        const uint32_t sb = sa + GA_ST_BYTES;
        int ka = kc0 + a_seg * 8;
        if (ka >= 2048) ka -= 2048;
        #pragma unroll
        for (int i = 0; i < 2; i++) {
            int row = a_row + i * 64;
            cp16(sa + (row * GA_STRIDE + a_seg * 8) * 2,
                 g_a1h + (size_t)(m0 + row) * 2048 + ka);
        }
        #pragma unroll
        for (int i = 0; i < 2; i++) {
            int row = b_row + i * 16;
            int kr = kc0 + row;
            int srow = (kr < 2048) ? (kr & 1023) : (kr - 1024);
            cp16(sb + (row * GB_STRIDE + b_seg * 8) * 2,
                 g_b1h + (size_t)srow * N1 + n0 + b_seg * 8);
        }
    };

    float acc[2][8][4];
    #pragma unroll
    for (int mi = 0; mi < 2; mi++)
        #pragma unroll
        for (int nj = 0; nj < 8; nj++)
            #pragma unroll
            for (int e = 0; e < 4; e++) acc[mi][nj][e] = 0.f;

    #pragma unroll
    for (int c = 0; c < GM_STAGES - 1; c++) { load_stage(c, c); cp_commit(); }

    for (int c = 0; c < kiters; c++) {
        cp_wait<GM_STAGES - 2>();
        __syncthreads();
        if (c + GM_STAGES - 1 < kiters)
            load_stage(c + GM_STAGES - 1, (c + GM_STAGES - 1) % GM_STAGES);
        cp_commit();

        const int s = c % GM_STAGES;
        const uint32_t sa = smb + s * GM_STAGE_BYTES;
        const uint32_t sb = sa + GA_ST_BYTES;
        #pragma unroll
        for (int ks = 0; ks < 2; ks++) {
            uint32_t af[2][4], bf[4][4];
            #pragma unroll
            for (int mi = 0; mi < 2; mi++)
                ldsm4(af[mi], sa + ((m_w + mi * 16 + (lane & 15)) * GA_STRIDE
                                    + ks * 16 + (lane >> 4) * 8) * 2);
            #pragma unroll
            for (int nj = 0; nj < 4; nj++)
                ldsm4t(bf[nj], sb + ((ks * 16 + (lane & 15)) * GB_STRIDE
                                     + n_w + nj * 16 + (lane >> 4) * 8) * 2);
            #pragma unroll
            for (int mi = 0; mi < 2; mi++)
                #pragma unroll
                for (int nj = 0; nj < 4; nj++) {
                    mma16816(acc[mi][nj * 2],     af[mi], &bf[nj][0]);
                    mma16816(acc[mi][nj * 2 + 1], af[mi], &bf[nj][2]);
                }
        }
    }

    const int r_in = lane >> 2;
    const int c_in = (lane & 3) * 2;
    #pragma unroll
    for (int nj = 0; nj < 8; nj++) {
        const int col = n0 + n_w + nj * 8 + c_in;
        float2 bb = *(const float2*)&g_bias1[col];
        #pragma unroll
        for (int mi = 0; mi < 2; mi++) {
            const int r0 = m0 + m_w + mi * 16 + r_in;
            float2 v0 = { acc[mi][nj][0] + bb.x, acc[mi][nj][1] + bb.y };
            float2 v1 = { acc[mi][nj][2] + bb.x, acc[mi][nj][3] + bb.y };
            *(float2*)(g_xall + (size_t)r0 * N1 + col)       = v0;
            *(float2*)(g_xall + (size_t)(r0 + 8) * N1 + col) = v1;
        }
    }
}

// ---------------- p3: mma GEMM 128x128x32, 4-stage, 2 CTA/SM (B wrapped) ----
__global__ void __launch_bounds__(256, 2) gemm_p3_mma(
    const float* __restrict__ b_out, float* __restrict__ out)
{
    constexpr int kiters = K2 / GM_BK;        // 64
    extern __shared__ char dynsm[];
    const int tid  = threadIdx.x;
    const int wid  = tid >> 5;
    const int lane = tid & 31;
    const int m0 = blockIdx.x * GM_BM;
    const int n0 = blockIdx.y * 128;
    const int m_w = (wid & 3) * 32;
    const int n_w = (wid >> 2) * 64;
    const uint32_t smb = smem_u32(dynsm);

    const int a_row = tid >> 2,  a_seg = tid & 3;
    const int b_row = tid >> 4,  b_seg = tid & 15;

    auto load_stage = [&](int chunk, int s) {
        const int kc0 = chunk * GM_BK;
        const uint32_t sa = smb + s * GM_STAGE_BYTES;
        const uint32_t sb = sa + GA_ST_BYTES;
        #pragma unroll
        for (int i = 0; i < 2; i++) {
            int row = a_row + i * 64;
            cp16(sa + (row * GA_STRIDE + a_seg * 8) * 2,
                 g_a2h + (size_t)(m0 + row) * K2 + kc0 + a_seg * 8);
        }
        #pragma unroll
        for (int i = 0; i < 2; i++) {
            int row = b_row + i * 16;
            int srow = (kc0 + row) & 1023;    // [Bh;Bh] logical -> [Bh] storage
            cp16(sb + (row * GB_STRIDE + b_seg * 8) * 2,
                 g_b2h + (size_t)srow * NV + n0 + b_seg * 8);
        }
    };

    float acc[2][8][4];
    #pragma unroll
    for (int mi = 0; mi < 2; mi++)
        #pragma unroll
        for (int nj = 0; nj < 8; nj++)
            #pragma unroll
            for (int e = 0; e < 4; e++) acc[mi][nj][e] = 0.f;

    #pragma unroll
    for (int c = 0; c < GM_STAGES - 1; c++) { load_stage(c, c); cp_commit(); }

    for (int c = 0; c < kiters; c++) {
        cp_wait<GM_STAGES - 2>();
        __syncthreads();
        if (c + GM_STAGES - 1 < kiters)
            load_stage(c + GM_STAGES - 1, (c + GM_STAGES - 1) % GM_STAGES);
        cp_commit();

        const int s = c % GM_STAGES;
        const uint32_t sa = smb + s * GM_STAGE_BYTES;
        const uint32_t sb = sa + GA_ST_BYTES;
        #pragma unroll
        for (int ks = 0; ks < 2; ks++) {
            uint32_t af[2][4], bf[4][4];
            #pragma unroll
            for (int mi = 0; mi < 2; mi++)
                ldsm4(af[mi], sa + ((m_w + mi * 16 + (lane & 15)) * GA_STRIDE
                                    + ks * 16 + (lane >> 4) * 8) * 2);
            #pragma unroll
            for (int nj = 0; nj < 4; nj++)
                ldsm4t(bf[nj], sb + ((ks * 16 + (lane & 15)) * GB_STRIDE
                                     + n_w + nj * 16 + (lane >> 4) * 8) * 2);
            #pragma unroll
            for (int mi = 0; mi < 2; mi++)
                #pragma unroll
                for (int nj = 0; nj < 4; nj++) {
                    mma16816(acc[mi][nj * 2],     af[mi], &bf[nj][0]);
                    mma16816(acc[mi][nj * 2 + 1], af[mi], &bf[nj][2]);
                }
        }
    }

    const int r_in = lane >> 2;
    const int c_in = (lane & 3) * 2;
    #pragma unroll
    for (int nj = 0; nj < 8; nj++) {
        const int col = n0 + n_w + nj * 8 + c_in;
        float2 bb = *(const float2*)&b_out[col];
        #pragma unroll
        for (int mi = 0; mi < 2; mi++) {
            const int r0 = m0 + m_w + mi * 16 + r_in;
            float2 v0 = { acc[mi][nj][0] + bb.x, acc[mi][nj][1] + bb.y };
            float2 v1 = { acc[mi][nj][2] + bb.x, acc[mi][nj][3] + bb.y };
            *(float2*)(out + (size_t)r0 * NV + col)       = v0;
            *(float2*)(out + (size_t)(r0 + 8) * NV + col) = v1;
        }
    }
}

// ---------------- phase 2: persistent recurrent kernel (512 threads) --------
// SMEM (floats): Us2 [k4=256][c=32][4] 128KB | hsm [k][b] 64KB | red [16][32][16] 32KB
#define REC_CTAS 128
#define REC_THREADS 512
#define US_FLOATS  32768
#define HS_FLOATS  16384
#define RED_FLOATS 8192
#define SMEM_REC_BYTES ((US_FLOATS + HS_FLOATS + RED_FLOATS) * 4)   // 229376

__global__ void __launch_bounds__(REC_THREADS, 1) lstm_rec(
    const float* __restrict__ u_f, const float* __restrict__ u_i,
    const float* __restrict__ u_c, const float* __restrict__ u_o)
{
    extern __shared__ float sm[];
    float* Us2 = sm;
    float* hsm = sm + US_FLOATS;
    float* red = sm + US_FLOATS + HS_FLOATS;
    const int tid  = threadIdx.x;
    const int lane = tid & 31;
    const int wid  = tid >> 5;       // warp = k-slice (16 slices of 64 k)
    const int cta  = blockIdx.x;

    // load + transpose this CTA's U slice: Us2[k4][c][j]
    {
        const float* umat[4] = {u_f, u_i, u_c, u_o};
        for (int i = tid; i < US_FLOATS; i += REC_THREADS) {
            int k = i >> 5, cc = i & 31;
            int gg = cc >> 3, jl = cc & 7;
            int k4 = k >> 2, j = k & 3;
            Us2[k4 * 128 + cc * 4 + j] = umat[gg][(size_t)k * H + cta * 8 + jl];
        }
    }
    __syncthreads();

    const int c2 = lane & 15;
    const int bh = lane >> 4;
    const int c0 = c2 * 2, c1 = c0 + 1;
    const int ks = wid;              // 0..15
    const uint32_t hsm_a = smem_u32(hsm);
    const float4* Us4 = (const float4*)Us2;
    const float4* h4  = (const float4*)hsm;
    float creg = 0.f;

    float pre[4];
    const int jloc_u = tid >> 4, b_u = tid & 15;
    if (tid < 128) {
        size_t row = (size_t)(b_u * TSTEPS + 0) * N1 + cta * 8 + jloc_u;
        #pragma unroll
        for (int gg = 0; gg < 4; gg++) pre[gg] = __ldg(&g_xall[row + gg * 1024]);
    }

    u64 acc[8];
    auto compute_range = [&](int k4beg, int k4end) {
        #pragma unroll 4
        for (int k4 = k4beg; k4 < k4end; k4++) {
            float4 u0 = Us4[k4 * 32 + c0];
            float4 u1 = Us4[k4 * 32 + c1];
            #pragma unroll
            for (int j = 0; j < 4; j++) {
                int k = k4 * 4 + j;
                float4 ha = h4[k * 4 + bh * 2];
                float4 hb = h4[k * 4 + bh * 2 + 1];
                u64 p0 = pk2(ha.x, ha.y), p1 = pk2(ha.z, ha.w);
                u64 p2 = pk2(hb.x, hb.y), p3 = pk2(hb.z, hb.w);
                float uj0 = ((const float*)&u0)[j];
                float uj1 = ((const float*)&u1)[j];
                u64 w0 = pk2(uj0, uj0), w1 = pk2(uj1, uj1);
                fma2(acc[0], w0, p0); fma2(acc[1], w0, p1);
                fma2(acc[2], w0, p2); fma2(acc[3], w0, p3);
                fma2(acc[4], w1, p0); fma2(acc[5], w1, p1);
                fma2(acc[6], w1, p2); fma2(acc[7], w1, p3);
            }
        }
    };

    for (int t = 0; t < TSTEPS; t++) {
        // per-warp stage of own 64-k slice (4 KB), 2 commit groups
        {
            const float* src = g_h + ks * 1024 + lane * 4;
            uint32_t dst = hsm_a + (ks * 1024 + lane * 4) * 4;
            #pragma unroll
            for (int j = 0; j < 4; j++)
                cp16(dst + j * 512, src + j * 128);
            cp_commit();
            #pragma unroll
            for (int j = 4; j < 8; j++)
                cp16(dst + j * 512, src + j * 128);
            cp_commit();
        }
        #pragma unroll
        for (int i = 0; i < 8; i++) acc[i] = 0ull;
        cp_wait<1>();
        __syncwarp();
        compute_range(ks * 16, ks * 16 + 8);
        cp_wait<0>();
        __syncwarp();
        compute_range(ks * 16 + 8, ks * 16 + 16);

        {
            float o[16];
            #pragma unroll
            for (int i = 0; i < 8; i++) upk2(o[2*i], o[2*i+1], acc[i]);
            float* r0 = red + (ks * 32 + c0) * 16 + bh * 8;
            float* r1 = red + (ks * 32 + c1) * 16 + bh * 8;
            *(float4*)(r0)     = *(float4*)&o[0];
            *(float4*)(r0 + 4) = *(float4*)&o[4];
            *(float4*)(r1)     = *(float4*)&o[8];
            *(float4*)(r1 + 4) = *(float4*)&o[12];
        }
        __syncthreads();

        // reduce + nonlinearity + state update + fused fp16 split A2 write
        if (tid < 128) {
            float s[4];
            #pragma unroll
            for (int gg = 0; gg < 4; gg++) {
                int cc = gg * 8 + jloc_u;
                float v = 0.f;
                #pragma unroll
                for (int kk = 0; kk < 16; kk++) v += red[(kk * 32 + cc) * 16 + b_u];
                s[gg] = v + pre[gg];
            }
            float ft   = 1.f / (1.f + __expf(-s[0]));
            float it   = 1.f / (1.f + __expf(-s[1]));
            float cand = tanhf(s[2]);
            float ot   = 1.f / (1.f + __expf(-s[3]));
            creg = ft * creg + it * cand;
            float hv = ot * tanhf(creg);
            int jglob = cta * 8 + jloc_u;
            g_h[jglob * NB + b_u] = hv;
            // fused p3-A conversion
            __half hi16 = __float2half(hv);
            __half lo16 = __float2half(hv - __half2float(hi16));
            __half* arow = g_a2h + (size_t)(b_u * TSTEPS + t) * K2;
            arow[jglob]        = hi16;
            arow[jglob + 1024] = lo16;
        }

        // prefetch next step's pre-activations (overlaps barrier wait)
        if (tid < 128 && t + 1 < TSTEPS) {
            size_t row = (size_t)(b_u * TSTEPS + t + 1) * N1 + cta * 8 + jloc_u;
            #pragma unroll
            for (int gg = 0; gg < 4; gg++) pre[gg] = __ldg(&g_xall[row + gg * 1024]);
        }

        // grid barrier (proven threadfence version)
        __syncthreads();
        if (tid == 0) {
            __threadfence();
            atomicAdd(&g_bar, 1u);
            const unsigned target = (unsigned)(REC_CTAS * (t + 1));
            int spins = 0;
            while (true) {
                unsigned v;
                asm volatile("ld.global.cg.u32 %0, [%1];" : "=r"(v) : "l"(&g_bar));
                if (v >= target) break;
                if (++spins > 8) __nanosleep(32);
            }
            __threadfence();
        }
        __syncthreads();
    }
}

__global__ void init_kernel() {
    int i = blockIdx.x * blockDim.x + threadIdx.x;
    if (i == 0) g_bar = 0u;
    if (i < H * NB) g_h[i] = 0.f;
}

// ---------------- launch ----------------------------------------------------
extern "C" void kernel_launch(void* const* d_in, const int* in_sizes, int n_in,
                              void* d_out, int out_size) {
    const int*   tokens = (const int*)d_in[0];
    const float* emb    = (const float*)d_in[1];
    const float* w_f = (const float*)d_in[2];
    const float* u_f = (const float*)d_in[3];
    const float* b_f = (const float*)d_in[4];
    const float* w_i = (const float*)d_in[5];
    const float* u_i = (const float*)d_in[6];
    const float* b_i = (const float*)d_in[7];
    const float* w_c = (const float*)d_in[8];
    const float* u_c = (const float*)d_in[9];
    const float* b_c = (const float*)d_in[10];
    const float* w_o = (const float*)d_in[11];
    const float* u_o = (const float*)d_in[12];
    const float* b_o = (const float*)d_in[13];
    const float* w_out = (const float*)d_in[14];
    const float* b_out = (const float*)d_in[15];
    float* out = (float*)d_out;

    cudaFuncSetAttribute(lstm_rec, cudaFuncAttributeMaxDynamicSharedMemorySize,
                         SMEM_REC_BYTES);
    cudaFuncSetAttribute(gemm_p1_mma, cudaFuncAttributeMaxDynamicSharedMemorySize,
                         GM_SMEM);
    cudaFuncSetAttribute(gemm_p3_mma, cudaFuncAttributeMaxDynamicSharedMemorySize,
                         GM_SMEM);

    init_kernel<<<64, 256>>>();
    conv_w2<<<(int)(((size_t)H * NV + 255) / 256), 256>>>(w_out);
    conv_w1<<<(int)(((size_t)H * N1 + 255) / 256), 256>>>(w_f, w_i, w_c, w_o,
                                                          b_f, b_i, b_c, b_o);
    conv_x<<<(int)(((size_t)BT * H + 255) / 256), 256>>>(tokens, emb);
    gemm_p1_mma<<<dim3(BT / GM_BM, N1 / 128), 256, GM_SMEM>>>();
    lstm_rec<<<REC_CTAS, REC_THREADS, SMEM_REC_BYTES>>>(u_f, u_i, u_c, u_o);
    gemm_p3_mma<<<dim3(BT / GM_BM, NV / 128), 256, GM_SMEM>>>(b_out, out);
}

// round 17
// speedup vs baseline: 1.0310x; 1.0310x over previous
#include <cuda_runtime.h>
#include <cuda_fp16.h>
#include <cstdint>

#define H   1024
#define NB  16
#define TSTEPS 256
#define BT  4096      // B*T
#define N1  4096      // 4*H
#define NV  32000
#define K2  2048      // p3: [Ah | Al] split-K
#define K1  3072      // p1: [xh | xl | xh] split-K

typedef unsigned long long u64;

// ---------------- scratch (device globals; no allocations allowed) ----------
__device__ float g_xall[(size_t)BT * N1];       // gate pre-activations (64 MB)
__device__ float g_hs[(size_t)BT * H];          // hidden states fp32 (16 MB)
__device__ float g_h[H * NB];                   // current h [k][b]
__device__ unsigned g_bar;                      // grid barrier
__device__ __half g_a2h[(size_t)BT * K2];       // p3 A: [m][Ah|Al] (16.8 MB)
__device__ __half g_b2h[(size_t)K2 * NV];       // p3 B: [Bh;Bh] (131 MB)
__device__ __half g_a1h[(size_t)BT * K1];       // p1 A: [m][xh|xl|xh] (25 MB)
__device__ __half g_b1h[(size_t)K1 * N1];       // p1 B: [Wh;Wh;Wl] (25 MB)
__device__ float  g_bias1[N1];                  // concat gate biases

// ---------------- packed f32x2 helpers --------------------------------------
__device__ __forceinline__ u64 pk2(float lo, float hi) {
    u64 r; asm("mov.b64 %0, {%1,%2};" : "=l"(r) : "f"(lo), "f"(hi)); return r;
}
__device__ __forceinline__ void fma2(u64 &d, u64 a, u64 b) {
    asm("fma.rn.f32x2 %0, %1, %2, %0;" : "+l"(d) : "l"(a), "l"(b));
}
__device__ __forceinline__ void upk2(float &lo, float &hi, u64 v) {
    asm("mov.b64 {%0,%1}, %2;" : "=f"(lo), "=f"(hi) : "l"(v));
}
__device__ __forceinline__ uint32_t smem_u32(const void* p) {
    uint32_t a;
    asm("{ .reg .u64 t; cvta.to.shared.u64 t, %1; cvt.u32.u64 %0, t; }"
        : "=r"(a) : "l"(p));
    return a;
}

// ---------------- cp.async helpers ------------------------------------------
__device__ __forceinline__ void cp16(uint32_t dst, const void* src) {
    asm volatile("cp.async.cg.shared.global [%0], [%1], 16;"
                 :: "r"(dst), "l"(src));
}
__device__ __forceinline__ void cp_commit() {
    asm volatile("cp.async.commit_group;");
}
template<int N> __device__ __forceinline__ void cp_wait() {
    asm volatile("cp.async.wait_group %0;" :: "n"(N));
}

// ---------------- mma helpers ------------------------------------------------
__device__ __forceinline__ void ldsm4(uint32_t* r, uint32_t addr) {
    asm volatile("ldmatrix.sync.aligned.m8n8.x4.shared.b16 {%0,%1,%2,%3}, [%4];"
                 : "=r"(r[0]), "=r"(r[1]), "=r"(r[2]), "=r"(r[3]) : "r"(addr));
}
__device__ __forceinline__ void ldsm4t(uint32_t* r, uint32_t addr) {
    asm volatile("ldmatrix.sync.aligned.m8n8.x4.trans.shared.b16 {%0,%1,%2,%3}, [%4];"
                 : "=r"(r[0]), "=r"(r[1]), "=r"(r[2]), "=r"(r[3]) : "r"(addr));
}
__device__ __forceinline__ void mma16816(float* d, const uint32_t* a,
                                         const uint32_t* b) {
    asm volatile(
        "mma.sync.aligned.m16n8k16.row.col.f32.f16.f16.f32 "
        "{%0,%1,%2,%3}, {%4,%5,%6,%7}, {%8,%9}, {%0,%1,%2,%3};"
        : "+f"(d[0]), "+f"(d[1]), "+f"(d[2]), "+f"(d[3])
        : "r"(a[0]), "r"(a[1]), "r"(a[2]), "r"(a[3]), "r"(b[0]), "r"(b[1]));
}

// ---------------- conversion kernels ----------------------------------------
__global__ void conv_w2(const float* __restrict__ w) {
    size_t idx = (size_t)blockIdx.x * blockDim.x + threadIdx.x;
    if (idx >= (size_t)H * NV) return;
    __half hv = __float2half(w[idx]);
    g_b2h[idx] = hv;                       // rows 0..1023: Bh (for Ah)
    g_b2h[idx + (size_t)H * NV] = hv;      // rows 1024..2047: Bh (for Al)
}

__global__ void conv_a2() {
    size_t idx = (size_t)blockIdx.x * blockDim.x + threadIdx.x;
    if (idx >= (size_t)BT * H) return;
    size_t m = idx >> 10, k = idx & 1023;
    float x = g_hs[idx];
    __half hi = __float2half(x);
    __half lo = __float2half(x - __half2float(hi));
    __half* row = g_a2h + m * K2;
    row[k] = hi; row[k + 1024] = lo;
}

// p1 B: [Wh;Wh;Wl] over concatenated gate columns; also bias concat
__global__ void conv_w1(const float* __restrict__ wf, const float* __restrict__ wi,
                        const float* __restrict__ wc, const float* __restrict__ wo,
                        const float* __restrict__ bf_, const float* __restrict__ bi_,
                        const float* __restrict__ bc_, const float* __restrict__ bo_) {
    size_t idx = (size_t)blockIdx.x * blockDim.x + threadIdx.x;
    if (idx < N1) {
        int g = (int)(idx >> 10), j = (int)(idx & 1023);
        const float* bs = (g == 0) ? bf_ : (g == 1) ? bi_ : (g == 2) ? bc_ : bo_;
        g_bias1[idx] = bs[j];
    }
    if (idx >= (size_t)H * N1) return;
    int k = (int)(idx >> 12);
    int col = (int)(idx & 4095);
    int g = col >> 10, j = col & 1023;
    const float* w = (g == 0) ? wf : (g == 1) ? wi : (g == 2) ? wc : wo;
    float x = w[(size_t)k * H + j];
    __half hi = __float2half(x);
    __half lo = __float2half(x - __half2float(hi));
    g_b1h[(size_t)k * N1 + col] = hi;
    g_b1h[(size_t)(k + 1024) * N1 + col] = hi;
    g_b1h[(size_t)(k + 2048) * N1 + col] = lo;
}

// p1 A: gather embedding + hi/lo split -> [xh|xl|xh]
__global__ void conv_x(const int* __restrict__ tokens, const float* __restrict__ emb) {
    size_t idx = (size_t)blockIdx.x * blockDim.x + threadIdx.x;
    if (idx >= (size_t)BT * H) return;
    size_t m = idx >> 10, k = idx & 1023;
    int tok = __ldg(&tokens[m]);
    float x = __ldg(&emb[(size_t)tok * H + k]);
    __half hi = __float2half(x);
    __half lo = __float2half(x - __half2float(hi));
    __half* row = g_a1h + m * K1;
    row[k] = hi; row[k + 1024] = lo; row[k + 2048] = hi;
}

// ---------------- generic mma GEMM: 128x128x32 tile, 5-stage, 2 CTA/SM ------
// MODE 0: p1  A=g_a1h (lda K1), B=g_b1h (ldb N1), bias=g_bias1, C=g_xall
// MODE 1: p3  A=g_a2h (lda K2), B=g_b2h (ldb NV), bias=arg, C=arg
#define GM_BM 128
#define GM_BK 32
#define GM_STAGES 5
#define GA_STRIDE 40                       // halves (80 B)
#define GB_STRIDE 136                      // halves (272 B)
#define GA_ST_BYTES (GM_BM * GA_STRIDE * 2)   // 10240
#define GB_ST_BYTES (GM_BK * GB_STRIDE * 2)   // 8704
#define GM_STAGE_BYTES (GA_ST_BYTES + GB_ST_BYTES)
#define GM_SMEM (GM_STAGES * GM_STAGE_BYTES)  // 94720 -> 2 CTA/SM (189 KB)

template<int MODE>
__global__ void __launch_bounds__(256, 2) gemm_mma(
    const float* __restrict__ bias_g, float* __restrict__ outg)
{
    constexpr int lda = MODE ? K2 : K1;
    constexpr int ldb = MODE ? NV : N1;
    constexpr int ldc = MODE ? NV : N1;
    constexpr int kiters = (MODE ? K2 : K1) / GM_BK;
    const __half* A = MODE ? g_a2h : g_a1h;
    const __half* B = MODE ? g_b2h : g_b1h;
    const float* bias = MODE ? bias_g : g_bias1;
    float* C = MODE ? outg : g_xall;

    extern __shared__ char dynsm[];
    const int tid  = threadIdx.x;
    const int wid  = tid >> 5;
    const int lane = tid & 31;
    const int m0 = blockIdx.x * GM_BM;
    const int n0 = blockIdx.y * 128;
    const int m_w = (wid & 3) * 32;       // warp M offset
    const int n_w = (wid >> 2) * 64;      // warp N offset
    const uint32_t smb = smem_u32(dynsm);

    const int a_row = tid >> 2,  a_seg = tid & 3;    // rows +0,+64
    const int b_row = tid >> 4,  b_seg = tid & 15;   // rows +0,+16

    auto load_stage = [&](int chunk, int s) {
        const int kc0 = chunk * GM_BK;
        const uint32_t sa = smb + s * GM_STAGE_BYTES;
        const uint32_t sb = sa + GA_ST_BYTES;
        #pragma unroll
        for (int i = 0; i < 2; i++) {
            int row = a_row + i * 64;
            cp16(sa + (row * GA_STRIDE + a_seg * 8) * 2,
                 A + (size_t)(m0 + row) * lda + kc0 + a_seg * 8);
        }
        #pragma unroll
        for (int i = 0; i < 2; i++) {
            int row = b_row + i * 16;
            cp16(sb + (row * GB_STRIDE + b_seg * 8) * 2,
                 B + (size_t)(kc0 + row) * ldb + n0 + b_seg * 8);
        }
    };

    float acc[2][8][4];
    #pragma unroll
    for (int mi = 0; mi < 2; mi++)
        #pragma unroll
        for (int nj = 0; nj < 8; nj++)
            #pragma unroll
            for (int e = 0; e < 4; e++) acc[mi][nj][e] = 0.f;

    #pragma unroll
    for (int c = 0; c < GM_STAGES - 1; c++) { load_stage(c, c); cp_commit(); }

    for (int c = 0; c < kiters; c++) {
        cp_wait<GM_STAGES - 2>();
        __syncthreads();
        if (c + GM_STAGES - 1 < kiters)
            load_stage(c + GM_STAGES - 1, (c + GM_STAGES - 1) % GM_STAGES);
        cp_commit();

        const int s = c % GM_STAGES;
        const uint32_t sa = smb + s * GM_STAGE_BYTES;
        const uint32_t sb = sa + GA_ST_BYTES;
        #pragma unroll
        for (int ks = 0; ks < 2; ks++) {
            uint32_t af[2][4], bf[4][4];
            #pragma unroll
            for (int mi = 0; mi < 2; mi++)
                ldsm4(af[mi], sa + ((m_w + mi * 16 + (lane & 15)) * GA_STRIDE
                                    + ks * 16 + (lane >> 4) * 8) * 2);
            #pragma unroll
            for (int nj = 0; nj < 4; nj++)
                ldsm4t(bf[nj], sb + ((ks * 16 + (lane & 15)) * GB_STRIDE
                                     + n_w + nj * 16 + (lane >> 4) * 8) * 2);
            #pragma unroll
            for (int mi = 0; mi < 2; mi++)
                #pragma unroll
                for (int nj = 0; nj < 4; nj++) {
                    mma16816(acc[mi][nj * 2],     af[mi], &bf[nj][0]);
                    mma16816(acc[mi][nj * 2 + 1], af[mi], &bf[nj][2]);
                }
        }
    }

    // epilogue: bias + fp32 store
    const int r_in = lane >> 2;
    const int c_in = (lane & 3) * 2;
    #pragma unroll
    for (int nj = 0; nj < 8; nj++) {
        const int col = n0 + n_w + nj * 8 + c_in;
        float2 bb = *(const float2*)&bias[col];
        #pragma unroll
        for (int mi = 0; mi < 2; mi++) {
            const int r0 = m0 + m_w + mi * 16 + r_in;
            float2 v0 = { acc[mi][nj][0] + bb.x, acc[mi][nj][1] + bb.y };
            float2 v1 = { acc[mi][nj][2] + bb.x, acc[mi][nj][3] + bb.y };
            *(float2*)(C + (size_t)r0 * ldc + col)       = v0;
            *(float2*)(C + (size_t)(r0 + 8) * ldc + col) = v1;
        }
    }
}

// ---------------- phase 2: persistent recurrent kernel ----------------------
// SMEM (floats): Us2 [k4=256][c=32][4] 128KB | hsm [k][b] 64KB | red 16KB
#define REC_CTAS 128
#define REC_THREADS 256
#define US_FLOATS  32768
#define HS_FLOATS  16384
#define RED_FLOATS 4096
#define SMEM_REC_BYTES ((US_FLOATS + HS_FLOATS + RED_FLOATS) * 4)

__global__ void __launch_bounds__(REC_THREADS, 1) lstm_rec(
    const float* __restrict__ u_f, const float* __restrict__ u_i,
    const float* __restrict__ u_c, const float* __restrict__ u_o)
{
    extern __shared__ float sm[];
    float* Us2 = sm;
    float* hsm = sm + US_FLOATS;
    float* red = sm + US_FLOATS + HS_FLOATS;
    const int tid  = threadIdx.x;
    const int lane = tid & 31;
    const int wid  = tid >> 5;       // warp == k-slice (8 slices of 128 k)
    const int cta  = blockIdx.x;

    {
        const float* umat[4] = {u_f, u_i, u_c, u_o};
        for (int i = tid; i < US_FLOATS; i += REC_THREADS) {
            int k = i >> 5, cc = i & 31;
            int gg = cc >> 3, jl = cc & 7;
            int k4 = k >> 2, j = k & 3;
            Us2[k4 * 128 + cc * 4 + j] = umat[gg][(size_t)k * H + cta * 8 + jl];
        }
    }
    __syncthreads();

    const int c2 = lane & 15;
    const int bh = lane >> 4;
    const int c0 = c2 * 2, c1 = c0 + 1;
    const int ks = wid;
    const uint32_t hsm_a = smem_u32(hsm);
    const float4* Us4 = (const float4*)Us2;
    const float4* h4  = (const float4*)hsm;
    float creg = 0.f;

    float pre[4];
    int jloc_u = tid >> 4, b_u = tid & 15;
    if (tid < 128) {
        size_t row = (size_t)(b_u * TSTEPS + 0) * N1 + cta * 8 + jloc_u;
        #pragma unroll
        for (int gg = 0; gg < 4; gg++) pre[gg] = __ldg(&g_xall[row + gg * 1024]);
    }

    u64 acc[8];
    auto compute_range = [&](int k4beg, int k4end) {
        #pragma unroll 4
        for (int k4 = k4beg; k4 < k4end; k4++) {
            float4 u0 = Us4[k4 * 32 + c0];
            float4 u1 = Us4[k4 * 32 + c1];
            #pragma unroll
            for (int j = 0; j < 4; j++) {
                int k = k4 * 4 + j;
                float4 ha = h4[k * 4 + bh * 2];
                float4 hb = h4[k * 4 + bh * 2 + 1];
                u64 p0 = pk2(ha.x, ha.y), p1 = pk2(ha.z, ha.w);
                u64 p2 = pk2(hb.x, hb.y), p3 = pk2(hb.z, hb.w);
                float uj0 = ((const float*)&u0)[j];
                float uj1 = ((const float*)&u1)[j];
                u64 w0 = pk2(uj0, uj0), w1 = pk2(uj1, uj1);
                fma2(acc[0], w0, p0); fma2(acc[1], w0, p1);
                fma2(acc[2], w0, p2); fma2(acc[3], w0, p3);
                fma2(acc[4], w1, p0); fma2(acc[5], w1, p1);
                fma2(acc[6], w1, p2); fma2(acc[7], w1, p3);
            }
        }
    };

    for (int t = 0; t < TSTEPS; t++) {
        // split-staged h: two cp groups, overlap 2nd group with 1st half compute
        {
            const float* src = g_h + ks * 2048 + lane * 4;
            uint32_t dst = hsm_a + ks * 8192 + lane * 16;
            #pragma unroll
            for (int i = 0; i < 8; i++)
                cp16(dst + i * 512, src + i * 128);
            cp_commit();
            #pragma unroll
            for (int i = 8; i < 16; i++)
                cp16(dst + i * 512, src + i * 128);
            cp_commit();
        }
        #pragma unroll
        for (int i = 0; i < 8; i++) acc[i] = 0ull;
        cp_wait<1>();
        __syncwarp();
        compute_range(ks * 32, ks * 32 + 16);
        cp_wait<0>();
        __syncwarp();
        compute_range(ks * 32 + 16, ks * 32 + 32);

        {
            float o[16];
            #pragma unroll
            for (int i = 0; i < 8; i++) upk2(o[2*i], o[2*i+1], acc[i]);
            float* r0 = red + (ks * 32 + c0) * 16 + bh * 8;
            float* r1 = red + (ks * 32 + c1) * 16 + bh * 8;
            *(float4*)(r0)     = *(float4*)&o[0];
            *(float4*)(r0 + 4) = *(float4*)&o[4];
            *(float4*)(r1)     = *(float4*)&o[8];
            *(float4*)(r1 + 4) = *(float4*)&o[12];
        }
        __syncthreads();

        if (tid < 128) {
            float s[4];
            #pragma unroll
            for (int gg = 0; gg < 4; gg++) {
                int cc = gg * 8 + jloc_u;
                float v = 0.f;
                #pragma unroll
                for (int kk = 0; kk < 8; kk++) v += red[(kk * 32 + cc) * 16 + b_u];
                s[gg] = v + pre[gg];
            }
            float ft   = 1.f / (1.f + __expf(-s[0]));
            float it   = 1.f / (1.f + __expf(-s[1]));
            float cand = tanhf(s[2]);
            float ot   = 1.f / (1.f + __expf(-s[3]));
            creg = ft * creg + it * cand;
            float hv = ot * tanhf(creg);
            int jglob = cta * 8 + jloc_u;
            g_h[jglob * NB + b_u] = hv;
            g_hs[(size_t)(b_u * TSTEPS + t) * H + jglob] = hv;
        }

        if (tid < 128 && t + 1 < TSTEPS) {
            size_t row = (size_t)(b_u * TSTEPS + t + 1) * N1 + cta * 8 + jloc_u;
            #pragma unroll
            for (int gg = 0; gg < 4; gg++) pre[gg] = __ldg(&g_xall[row + gg * 1024]);
        }

        __syncthreads();
        if (tid == 0) {
            __threadfence();
            atomicAdd(&g_bar, 1u);
            const unsigned target = (unsigned)(REC_CTAS * (t + 1));
            int spins = 0;
            while (true) {
                unsigned v;
                asm volatile("ld.global.cg.u32 %0, [%1];" : "=r"(v) : "l"(&g_bar));
                if (v >= target) break;
                if (++spins > 8) __nanosleep(32);
            }
            __threadfence();
        }
        __syncthreads();
    }
}

__global__ void init_kernel() {
    int i = blockIdx.x * blockDim.x + threadIdx.x;
    if (i == 0) g_bar = 0u;
    if (i < H * NB) g_h[i] = 0.f;
}

// ---------------- launch ----------------------------------------------------
extern "C" void kernel_launch(void* const* d_in, const int* in_sizes, int n_in,
                              void* d_out, int out_size) {
    const int*   tokens = (const int*)d_in[0];
    const float* emb    = (const float*)d_in[1];
    const float* w_f = (const float*)d_in[2];
    const float* u_f = (const float*)d_in[3];
    const float* b_f = (const float*)d_in[4];
    const float* w_i = (const float*)d_in[5];
    const float* u_i = (const float*)d_in[6];
    const float* b_i = (const float*)d_in[7];
    const float* w_c = (const float*)d_in[8];
    const float* u_c = (const float*)d_in[9];
    const float* b_c = (const float*)d_in[10];
    const float* w_o = (const float*)d_in[11];
    const float* u_o = (const float*)d_in[12];
    const float* b_o = (const float*)d_in[13];
    const float* w_out = (const float*)d_in[14];
    const float* b_out = (const float*)d_in[15];
    float* out = (float*)d_out;

    cudaFuncSetAttribute(lstm_rec, cudaFuncAttributeMaxDynamicSharedMemorySize,
                         SMEM_REC_BYTES);
    cudaFuncSetAttribute(gemm_mma<0>, cudaFuncAttributeMaxDynamicSharedMemorySize,
                         GM_SMEM);
    cudaFuncSetAttribute(gemm_mma<1>, cudaFuncAttributeMaxDynamicSharedMemorySize,
                         GM_SMEM);

    init_kernel<<<64, 256>>>();
    conv_w2<<<(int)(((size_t)H * NV + 255) / 256), 256>>>(w_out);
    conv_w1<<<(int)(((size_t)H * N1 + 255) / 256), 256>>>(w_f, w_i, w_c, w_o,
                                                          b_f, b_i, b_c, b_o);
    conv_x<<<(int)(((size_t)BT * H + 255) / 256), 256>>>(tokens, emb);
    gemm_mma<0><<<dim3(BT / GM_BM, N1 / 128), 256, GM_SMEM>>>(nullptr, nullptr);
    lstm_rec<<<REC_CTAS, REC_THREADS, SMEM_REC_BYTES>>>(u_f, u_i, u_c, u_o);
    conv_a2<<<(int)(((size_t)BT * H + 255) / 256), 256>>>();
    gemm_mma<1><<<dim3(BT / GM_BM, NV / 128), 256, GM_SMEM>>>(b_out, out);
}